// round 1
// baseline (speedup 1.0000x reference)
#include <cuda_runtime.h>
#include <cuda_fp16.h>
#include <cstdint>

#define HID 1024
#define VOC 32000
#define NL  3
#define NB  64
#define NT  32
#define K3H (3*HID)

// ---------------- device scratch (static, allocation-free) ----------------
__device__ __align__(16) __half g_Wih16[NL * K3H * HID];
__device__ __align__(16) __half g_Whh16[NL * K3H * HID];
__device__ __align__(16) __half g_Wout16[VOC * HID];
__device__ __align__(16) __half g_x16a[NB * NT * HID];
__device__ __align__(16) __half g_x16b[NB * NT * HID];
__device__ __align__(16) float  g_xp[NB * NT * K3H];
__device__ __align__(16) float  g_h[NB * HID];
__device__ __align__(16) __half g_h16a[NB * HID];
__device__ __align__(16) __half g_h16b[NB * HID];

// ---------------- helpers ----------------
__device__ __forceinline__ uint32_t smem_u32(const void* p) {
    return (uint32_t)__cvta_generic_to_shared(p);
}
__device__ __forceinline__ void cp16(uint32_t d, const void* s) {
    asm volatile("cp.async.cg.shared.global [%0], [%1], 16;\n" :: "r"(d), "l"(s));
}
__device__ __forceinline__ void cp_commit() {
    asm volatile("cp.async.commit_group;\n" ::: "memory");
}
__device__ __forceinline__ void mma16816(float* c, const uint32_t* a, const uint32_t* b) {
    asm volatile(
        "mma.sync.aligned.m16n8k16.row.col.f32.f16.f16.f32 "
        "{%0,%1,%2,%3},{%4,%5,%6,%7},{%8,%9},{%0,%1,%2,%3};\n"
        : "+f"(c[0]), "+f"(c[1]), "+f"(c[2]), "+f"(c[3])
        : "r"(a[0]), "r"(a[1]), "r"(a[2]), "r"(a[3]), "r"(b[0]), "r"(b[1]));
}

// ---------------- f32 -> f16 weight convert ----------------
__global__ void k_cvt(const float* __restrict__ src, int dstSel, int n) {
    int i = (blockIdx.x * 256 + threadIdx.x) * 4;
    if (i >= n) return;
    __half* dst = (dstSel == 0) ? g_Wih16 : (dstSel == 1) ? g_Whh16 : g_Wout16;
    float4 v = *(const float4*)(src + i);
    *(__half2*)(dst + i)     = __floats2half2_rn(v.x, v.y);
    *(__half2*)(dst + i + 2) = __floats2half2_rn(v.z, v.w);
}

// ---------------- embedding + relu -> x16a ----------------
__global__ void k_embed(const float* __restrict__ emb, const int* __restrict__ target) {
    int row = blockIdx.x;           // 0..NB*NT-1
    int b = row >> 5, t = row & 31; // NT = 32
    int id = (t == 0) ? 0 : target[b * NT + t - 1];
    const float* src = emb + (size_t)id * HID;
    __half* dst = g_x16a + (size_t)row * HID;
    int i = threadIdx.x * 4;
    float4 v = *(const float4*)(src + i);
    *(__half2*)(dst + i)     = __floats2half2_rn(fmaxf(v.x, 0.f), fmaxf(v.y, 0.f));
    *(__half2*)(dst + i + 2) = __floats2half2_rn(fmaxf(v.z, 0.f), fmaxf(v.w, 0.f));
}

// ---------------- h0 init (fp32 + fp16 copies) ----------------
__global__ void k_hinit(const float* __restrict__ src) {
    int i = (blockIdx.x * 256 + threadIdx.x) * 4;
    float4 v = *(const float4*)(src + i);
    *(float4*)(g_h + i) = v;
    *(__half2*)(g_h16a + i)     = __floats2half2_rn(v.x, v.y);
    *(__half2*)(g_h16a + i + 2) = __floats2half2_rn(v.z, v.w);
}

// ---------------- generic fp16 MMA GEMM: C[M,N] = A[M,K] @ B[N,K]^T + bias ----------------
// BM=64, BN=64, BK=32, 256 threads (8 warps, warp tile 32x16)
__global__ __launch_bounds__(256) void k_gemm(int aSel, int bSel, const float* __restrict__ bias,
                                              int cSel, float* __restrict__ Cext, int ldc) {
    __shared__ __half sA[2][64 * 40];
    __shared__ __half sB[2][64 * 40];
    const __half* A  = (aSel == 0) ? g_x16a : g_x16b;
    const __half* Bw = (bSel < 3) ? (g_Wih16 + (size_t)bSel * K3H * HID) : g_Wout16;
    float* C = (cSel == 0) ? g_xp : Cext;
    const int Kdim = HID;

    const int tid = threadIdx.x;
    const int bn = blockIdx.x, bm = blockIdx.y;
    const int lane = tid & 31, warp = tid >> 5;
    const int g = lane >> 2, tg = lane & 3;
    const int wy = warp >> 2, wx = warp & 3;

    const int ldr = tid >> 2;          // 0..63
    const int seg = (tid & 3) * 8;     // half offset
    const __half* gA = A  + (size_t)(bm * 64 + ldr) * Kdim + seg;
    const __half* gB = Bw + (size_t)(bn * 64 + ldr) * Kdim + seg;
    const uint32_t dA = smem_u32(&sA[0][ldr * 40 + seg]);
    const uint32_t dB = smem_u32(&sB[0][ldr * 40 + seg]);
    const int bufStride = 64 * 40 * 2; // bytes

    const int NK = Kdim >> 5;
    cp16(dA, gA); cp16(dB, gB); cp_commit();

    float acc[2][2][4] = {};
    for (int kc = 0; kc < NK; ++kc) {
        int buf = kc & 1;
        if (kc + 1 < NK) {
            int nb = buf ^ 1;
            cp16(dA + nb * bufStride, gA + (kc + 1) * 32);
            cp16(dB + nb * bufStride, gB + (kc + 1) * 32);
            cp_commit();
            asm volatile("cp.async.wait_group 1;\n" ::: "memory");
        } else {
            asm volatile("cp.async.wait_group 0;\n" ::: "memory");
        }
        __syncthreads();
        const __half* As = sA[buf];
        const __half* Bs = sB[buf];
#pragma unroll
        for (int kk = 0; kk < 32; kk += 16) {
            uint32_t a[2][4], bb[2][2];
#pragma unroll
            for (int mt = 0; mt < 2; ++mt) {
                int r0 = wy * 32 + mt * 16 + g;
                a[mt][0] = *(const uint32_t*)&As[r0 * 40 + kk + tg * 2];
                a[mt][1] = *(const uint32_t*)&As[(r0 + 8) * 40 + kk + tg * 2];
                a[mt][2] = *(const uint32_t*)&As[r0 * 40 + kk + tg * 2 + 8];
                a[mt][3] = *(const uint32_t*)&As[(r0 + 8) * 40 + kk + tg * 2 + 8];
            }
#pragma unroll
            for (int nt = 0; nt < 2; ++nt) {
                int c0 = wx * 16 + nt * 8 + g;
                bb[nt][0] = *(const uint32_t*)&Bs[c0 * 40 + kk + tg * 2];
                bb[nt][1] = *(const uint32_t*)&Bs[c0 * 40 + kk + tg * 2 + 8];
            }
#pragma unroll
            for (int mt = 0; mt < 2; ++mt)
#pragma unroll
                for (int nt = 0; nt < 2; ++nt)
                    mma16816(acc[mt][nt], a[mt], bb[nt]);
        }
        __syncthreads();
    }

#pragma unroll
    for (int mt = 0; mt < 2; ++mt) {
#pragma unroll
        for (int nt = 0; nt < 2; ++nt) {
            int row = bm * 64 + wy * 32 + mt * 16 + g;
            int col = bn * 64 + wx * 16 + nt * 8 + tg * 2;
            float b0 = bias[col], b1 = bias[col + 1];
            *(float2*)&C[(size_t)row * ldc + col] =
                make_float2(acc[mt][nt][0] + b0, acc[mt][nt][1] + b1);
            *(float2*)&C[(size_t)(row + 8) * ldc + col] =
                make_float2(acc[mt][nt][2] + b0, acc[mt][nt][3] + b1);
        }
    }
}

// ---------------- fused GRU step: hp GEMM + gates + h update, one kernel per timestep ----------------
// grid = 64 blocks; block cblk computes hidden cols [cblk*16, +16) for gates r,z,n
__global__ __launch_bounds__(256) void k_gru_step(int l, const float* __restrict__ bhh,
                                                  int t, float* __restrict__ finals) {
    __shared__ __half sA[2][64 * 40];
    __shared__ __half sB[2][48 * 40];
    __shared__ float hp_s[64 * 50];

    const __half* Whh = g_Whh16 + (size_t)l * K3H * HID;
    const __half* h16in  = (t & 1) ? g_h16b : g_h16a;
    __half* h16out       = (t & 1) ? g_h16a : g_h16b;
    __half* y16 = (l == 1) ? g_x16a : g_x16b;

    const int tid = threadIdx.x;
    const int cblk = blockIdx.x; // 0..63
    const int lane = tid & 31, warp = tid >> 5;
    const int g = lane >> 2, tg = lane & 3;
    const int wm = warp >> 1, wn = warp & 1;

    const int ldr = tid >> 2;
    const int seg = (tid & 3) * 8;
    const __half* gA = h16in + (size_t)ldr * HID + seg;
    const uint32_t dA = smem_u32(&sA[0][ldr * 40 + seg]);
    const bool doB = tid < 192;
    const int gate = ldr >> 4;
    const int grow = gate * HID + cblk * 16 + (ldr & 15);
    const __half* gB = Whh + (size_t)grow * HID + seg;
    const uint32_t dB = smem_u32(&sB[0][ldr * 40 + seg]);
    const int strA = 64 * 40 * 2, strB = 48 * 40 * 2;

    cp16(dA, gA);
    if (doB) cp16(dB, gB);
    cp_commit();

    float acc[3][4] = {};
    const int NK = HID / 32;
    for (int kc = 0; kc < NK; ++kc) {
        int buf = kc & 1;
        if (kc + 1 < NK) {
            int nb = buf ^ 1;
            cp16(dA + nb * strA, gA + (kc + 1) * 32);
            if (doB) cp16(dB + nb * strB, gB + (kc + 1) * 32);
            cp_commit();
            asm volatile("cp.async.wait_group 1;\n" ::: "memory");
        } else {
            asm volatile("cp.async.wait_group 0;\n" ::: "memory");
        }
        __syncthreads();
        const __half* As = sA[buf];
        const __half* Bs = sB[buf];
#pragma unroll
        for (int kk = 0; kk < 32; kk += 16) {
            uint32_t a[4], bb[3][2];
            int r0 = wm * 16 + g;
            a[0] = *(const uint32_t*)&As[r0 * 40 + kk + tg * 2];
            a[1] = *(const uint32_t*)&As[(r0 + 8) * 40 + kk + tg * 2];
            a[2] = *(const uint32_t*)&As[r0 * 40 + kk + tg * 2 + 8];
            a[3] = *(const uint32_t*)&As[(r0 + 8) * 40 + kk + tg * 2 + 8];
#pragma unroll
            for (int nt = 0; nt < 3; ++nt) {
                int c0 = wn * 24 + nt * 8 + g;
                bb[nt][0] = *(const uint32_t*)&Bs[c0 * 40 + kk + tg * 2];
                bb[nt][1] = *(const uint32_t*)&Bs[c0 * 40 + kk + tg * 2 + 8];
            }
#pragma unroll
            for (int nt = 0; nt < 3; ++nt) mma16816(acc[nt], a, bb[nt]);
        }
        __syncthreads();
    }

    // stage hp (64 x 48) through smem so gate triples meet in one thread
#pragma unroll
    for (int nt = 0; nt < 3; ++nt) {
        int row = wm * 16 + g, col = wn * 24 + nt * 8 + tg * 2;
        *(float2*)&hp_s[row * 50 + col]       = make_float2(acc[nt][0], acc[nt][1]);
        *(float2*)&hp_s[(row + 8) * 50 + col] = make_float2(acc[nt][2], acc[nt][3]);
    }
    __syncthreads();

#pragma unroll
    for (int i = 0; i < 4; ++i) {
        int idx = tid + i * 256;        // 0..1023
        int b = idx >> 4, jl = idx & 15;
        int j = cblk * 16 + jl;
        size_t xbase = ((size_t)(b * NT + t)) * K3H;
        float hr = hp_s[b * 50 + jl]      + bhh[j];
        float hz = hp_s[b * 50 + 16 + jl] + bhh[HID + j];
        float hn = hp_s[b * 50 + 32 + jl] + bhh[2 * HID + j];
        float r = 1.f / (1.f + __expf(-(g_xp[xbase + j] + hr)));
        float z = 1.f / (1.f + __expf(-(g_xp[xbase + HID + j] + hz)));
        float nn = tanhf(g_xp[xbase + 2 * HID + j] + r * hn);
        float ho = g_h[b * HID + j];
        float hnew = (1.f - z) * nn + z * ho;
        g_h[b * HID + j] = hnew;
        h16out[b * HID + j] = __float2half(hnew);
        y16[((size_t)(b * NT + t)) * HID + j] = __float2half(hnew);
        if (t == NT - 1) finals[b * HID + j] = hnew;
    }
}

// ---------------- in-place log_softmax over V per row ----------------
__global__ __launch_bounds__(1024) void k_logsoftmax(float* __restrict__ p) {
    float* base = p + (size_t)blockIdx.x * VOC;
    const int tid = threadIdx.x;
    const int warp = tid >> 5, lane = tid & 31;
    __shared__ float red[32];

    float v[32];
    float m = -1e30f;
#pragma unroll
    for (int i = 0; i < 32; ++i) {
        int idx = tid + i * 1024;
        v[i] = (idx < VOC) ? base[idx] : -1e30f;
        m = fmaxf(m, v[i]);
    }
#pragma unroll
    for (int off = 16; off; off >>= 1) m = fmaxf(m, __shfl_xor_sync(0xffffffffu, m, off));
    if (lane == 0) red[warp] = m;
    __syncthreads();
    if (warp == 0) {
        float x = red[lane];
#pragma unroll
        for (int off = 16; off; off >>= 1) x = fmaxf(x, __shfl_xor_sync(0xffffffffu, x, off));
        red[lane] = x;
    }
    __syncthreads();
    m = red[0];
    __syncthreads();

    float s = 0.f;
#pragma unroll
    for (int i = 0; i < 32; ++i) s += __expf(v[i] - m);
#pragma unroll
    for (int off = 16; off; off >>= 1) s += __shfl_xor_sync(0xffffffffu, s, off);
    if (lane == 0) red[warp] = s;
    __syncthreads();
    if (warp == 0) {
        float x = red[lane];
#pragma unroll
        for (int off = 16; off; off >>= 1) x += __shfl_xor_sync(0xffffffffu, x, off);
        red[lane] = x;
    }
    __syncthreads();
    s = red[0];

    float lse = m + logf(s);
#pragma unroll
    for (int i = 0; i < 32; ++i) {
        int idx = tid + i * 1024;
        if (idx < VOC) base[idx] = v[i] - lse;
    }
}

// ---------------- launch ----------------
extern "C" void kernel_launch(void* const* d_in, const int* in_sizes, int n_in,
                              void* d_out, int out_size) {
    const float* enc_hidden = (const float*)d_in[1];
    const int*   target     = (const int*)d_in[2];
    const float* emb        = (const float*)d_in[3];
    const float* W_ih       = (const float*)d_in[4];
    const float* W_hh       = (const float*)d_in[5];
    const float* b_ih       = (const float*)d_in[6];
    const float* b_hh       = (const float*)d_in[7];
    const float* W_out      = (const float*)d_in[8];
    const float* b_out      = (const float*)d_in[9];
    float* out = (float*)d_out;

    // 1) convert weights to fp16
    {
        int n1 = NL * K3H * HID;
        k_cvt<<<(n1 / 4 + 255) / 256, 256>>>(W_ih, 0, n1);
        k_cvt<<<(n1 / 4 + 255) / 256, 256>>>(W_hh, 1, n1);
        int n2 = VOC * HID;
        k_cvt<<<(n2 / 4 + 255) / 256, 256>>>(W_out, 2, n2);
    }

    // 2) embedding + relu
    k_embed<<<NB * NT, 256>>>(emb, target);

    // 3) layers
    for (int l = 0; l < NL; ++l) {
        k_hinit<<<(NB * HID / 4) / 256, 256>>>(enc_hidden + (size_t)l * NB * HID);
        int aSel = (l == 1) ? 1 : 0;
        k_gemm<<<dim3(K3H / 64, (NB * NT) / 64), 256>>>(aSel, l, b_ih + (size_t)l * K3H,
                                                        0, nullptr, K3H);
        float* finals = out + (size_t)NB * NT * VOC + (size_t)l * NB * HID;
        for (int t = 0; t < NT; ++t) {
            k_gru_step<<<HID / 16, 256>>>(l, b_hh + (size_t)l * K3H, t, finals);
        }
    }

    // 4) output GEMM (logits into d_out) + log_softmax in place
    k_gemm<<<dim3(VOC / 64, (NB * NT) / 64), 256>>>(1, 3, b_out, 1, out, VOC);
    k_logsoftmax<<<NB * NT, 1024>>>(out);
}

// round 2
// speedup vs baseline: 1.0932x; 1.0932x over previous
#include <cuda_runtime.h>
#include <cuda_fp16.h>
#include <cstdint>

#define HID 1024
#define VOC 32000
#define NL  3
#define NB  64
#define NT  32
#define K3H (3*HID)

// ---------------- device scratch (static, allocation-free) ----------------
__device__ __align__(16) __half g_Wih16[NL * K3H * HID];
__device__ __align__(16) __half g_Whh16[NL * K3H * HID];
__device__ __align__(16) __half g_Wout16[VOC * HID];
__device__ __align__(16) __half g_x16a[NB * NT * HID];
__device__ __align__(16) __half g_x16b[NB * NT * HID];
__device__ __align__(16) float  g_xp[NB * NT * K3H];
__device__ __align__(16) float  g_h[NB * HID];
__device__ __align__(16) __half g_h16a[NB * HID];
__device__ __align__(16) __half g_h16b[NB * HID];

// grid barrier state (generation-based; never needs host reset)
__device__ unsigned g_bar_cnt = 0;
__device__ unsigned g_bar_gen = 0;

// ---------------- helpers ----------------
__device__ __forceinline__ uint32_t smem_u32(const void* p) {
    return (uint32_t)__cvta_generic_to_shared(p);
}
__device__ __forceinline__ void cp16(uint32_t d, const void* s) {
    asm volatile("cp.async.cg.shared.global [%0], [%1], 16;\n" :: "r"(d), "l"(s));
}
__device__ __forceinline__ void cp_commit() {
    asm volatile("cp.async.commit_group;\n" ::: "memory");
}
__device__ __forceinline__ void mma16816(float* c, const uint32_t* a, const uint32_t* b) {
    asm volatile(
        "mma.sync.aligned.m16n8k16.row.col.f32.f16.f16.f32 "
        "{%0,%1,%2,%3},{%4,%5,%6,%7},{%8,%9},{%0,%1,%2,%3};\n"
        : "+f"(c[0]), "+f"(c[1]), "+f"(c[2]), "+f"(c[3])
        : "r"(a[0]), "r"(a[1]), "r"(a[2]), "r"(a[3]), "r"(b[0]), "r"(b[1]));
}

__device__ __forceinline__ void grid_sync(unsigned target) {
    __syncthreads();
    if (threadIdx.x == 0) {
        __threadfence();
        unsigned a = atomicAdd(&g_bar_cnt, 1);
        if (a == gridDim.x - 1) {
            g_bar_cnt = 0;
            __threadfence();
            atomicExch(&g_bar_gen, target);
        } else {
            while (*(volatile unsigned*)&g_bar_gen < target) { }
        }
        __threadfence();
    }
    __syncthreads();
}

// ---------------- f32 -> f16 weight convert ----------------
__global__ void k_cvt(const float* __restrict__ src, int dstSel, int n) {
    int i = (blockIdx.x * 256 + threadIdx.x) * 4;
    if (i >= n) return;
    __half* dst = (dstSel == 0) ? g_Wih16 : (dstSel == 1) ? g_Whh16 : g_Wout16;
    float4 v = *(const float4*)(src + i);
    *(__half2*)(dst + i)     = __floats2half2_rn(v.x, v.y);
    *(__half2*)(dst + i + 2) = __floats2half2_rn(v.z, v.w);
}

// ---------------- embedding + relu -> x16a ----------------
__global__ void k_embed(const float* __restrict__ emb, const int* __restrict__ target) {
    int row = blockIdx.x;           // 0..NB*NT-1
    int b = row >> 5, t = row & 31; // NT = 32
    int id = (t == 0) ? 0 : target[b * NT + t - 1];
    const float* src = emb + (size_t)id * HID;
    __half* dst = g_x16a + (size_t)row * HID;
    int i = threadIdx.x * 4;
    float4 v = *(const float4*)(src + i);
    *(__half2*)(dst + i)     = __floats2half2_rn(fmaxf(v.x, 0.f), fmaxf(v.y, 0.f));
    *(__half2*)(dst + i + 2) = __floats2half2_rn(fmaxf(v.z, 0.f), fmaxf(v.w, 0.f));
}

// ---------------- h0 init (fp32 + fp16 copies) ----------------
__global__ void k_hinit(const float* __restrict__ src) {
    int i = (blockIdx.x * 256 + threadIdx.x) * 4;
    float4 v = *(const float4*)(src + i);
    *(float4*)(g_h + i) = v;
    *(__half2*)(g_h16a + i)     = __floats2half2_rn(v.x, v.y);
    *(__half2*)(g_h16a + i + 2) = __floats2half2_rn(v.z, v.w);
}

// ---------------- generic fp16 MMA GEMM: C[M,N] = A[M,K] @ B[N,K]^T + bias ----------------
// BM=64, BN=64, BK=32, 256 threads (8 warps, warp tile 32x16)
__global__ __launch_bounds__(256) void k_gemm(int aSel, int bSel, const float* __restrict__ bias,
                                              int cSel, float* __restrict__ Cext, int ldc) {
    __shared__ __half sA[2][64 * 40];
    __shared__ __half sB[2][64 * 40];
    const __half* A  = (aSel == 0) ? g_x16a : g_x16b;
    const __half* Bw = (bSel < 3) ? (g_Wih16 + (size_t)bSel * K3H * HID) : g_Wout16;
    float* C = (cSel == 0) ? g_xp : Cext;
    const int Kdim = HID;

    const int tid = threadIdx.x;
    const int bn = blockIdx.x, bm = blockIdx.y;
    const int lane = tid & 31, warp = tid >> 5;
    const int g = lane >> 2, tg = lane & 3;
    const int wy = warp >> 2, wx = warp & 3;

    const int ldr = tid >> 2;          // 0..63
    const int seg = (tid & 3) * 8;     // half offset
    const __half* gA = A  + (size_t)(bm * 64 + ldr) * Kdim + seg;
    const __half* gB = Bw + (size_t)(bn * 64 + ldr) * Kdim + seg;
    const uint32_t dA = smem_u32(&sA[0][ldr * 40 + seg]);
    const uint32_t dB = smem_u32(&sB[0][ldr * 40 + seg]);
    const int bufStride = 64 * 40 * 2; // bytes

    const int NK = Kdim >> 5;
    cp16(dA, gA); cp16(dB, gB); cp_commit();

    float acc[2][2][4] = {};
    for (int kc = 0; kc < NK; ++kc) {
        int buf = kc & 1;
        if (kc + 1 < NK) {
            int nb = buf ^ 1;
            cp16(dA + nb * bufStride, gA + (kc + 1) * 32);
            cp16(dB + nb * bufStride, gB + (kc + 1) * 32);
            cp_commit();
            asm volatile("cp.async.wait_group 1;\n" ::: "memory");
        } else {
            asm volatile("cp.async.wait_group 0;\n" ::: "memory");
        }
        __syncthreads();
        const __half* As = sA[buf];
        const __half* Bs = sB[buf];
#pragma unroll
        for (int kk = 0; kk < 32; kk += 16) {
            uint32_t a[2][4], bb[2][2];
#pragma unroll
            for (int mt = 0; mt < 2; ++mt) {
                int r0 = wy * 32 + mt * 16 + g;
                a[mt][0] = *(const uint32_t*)&As[r0 * 40 + kk + tg * 2];
                a[mt][1] = *(const uint32_t*)&As[(r0 + 8) * 40 + kk + tg * 2];
                a[mt][2] = *(const uint32_t*)&As[r0 * 40 + kk + tg * 2 + 8];
                a[mt][3] = *(const uint32_t*)&As[(r0 + 8) * 40 + kk + tg * 2 + 8];
            }
#pragma unroll
            for (int nt = 0; nt < 2; ++nt) {
                int c0 = wx * 16 + nt * 8 + g;
                bb[nt][0] = *(const uint32_t*)&Bs[c0 * 40 + kk + tg * 2];
                bb[nt][1] = *(const uint32_t*)&Bs[c0 * 40 + kk + tg * 2 + 8];
            }
#pragma unroll
            for (int mt = 0; mt < 2; ++mt)
#pragma unroll
                for (int nt = 0; nt < 2; ++nt)
                    mma16816(acc[mt][nt], a[mt], bb[nt]);
        }
        __syncthreads();
    }

#pragma unroll
    for (int mt = 0; mt < 2; ++mt) {
#pragma unroll
        for (int nt = 0; nt < 2; ++nt) {
            int row = bm * 64 + wy * 32 + mt * 16 + g;
            int col = bn * 64 + wx * 16 + nt * 8 + tg * 2;
            float b0 = bias[col], b1 = bias[col + 1];
            *(float2*)&C[(size_t)row * ldc + col] =
                make_float2(acc[mt][nt][0] + b0, acc[mt][nt][1] + b1);
            *(float2*)&C[(size_t)(row + 8) * ldc + col] =
                make_float2(acc[mt][nt][2] + b0, acc[mt][nt][3] + b1);
        }
    }
}

// ---------------- persistent GRU scan: all 32 timesteps of one layer ----------------
// grid = 64 blocks x 256 threads (all co-resident). Block cblk owns hidden cols
// [cblk*16, +16) for gates r,z,n. W_hh slice (48x1024 fp16) cached in smem once.
// Per timestep: stream h (64x1024 fp16) in 32-K chunks, 3-deep cp.async pipeline,
// then fused gate epilogue + device-wide barrier.
#define SCAN_SMEM (48*1032*2 + 3*2560*2 + 64*50*4)
__global__ __launch_bounds__(256) void k_gru_scan(int l, const float* __restrict__ bhh,
                                                  float* __restrict__ finals) {
    extern __shared__ __align__(16) char smem_raw[];
    __half* Bs = (__half*)smem_raw;          // 48 x 1032 (K-contig, 8-half pad)
    __half* As = Bs + 48 * 1032;             // 3 bufs of 64 x 40
    float* hp_s = (float*)(As + 3 * 2560);   // 64 x 50

    const __half* Whh = g_Whh16 + (size_t)l * K3H * HID;
    __half* y16 = (l == 1) ? g_x16a : g_x16b;

    const int tid = threadIdx.x;
    const int cblk = blockIdx.x; // 0..63
    const int lane = tid & 31, warp = tid >> 5;
    const int g = lane >> 2, tg = lane & 3;
    const int wm = warp >> 1, wn = warp & 1;

    unsigned bar_t = *(volatile unsigned*)&g_bar_gen;

    // load W_hh slice once: 48 rows x 1024 halves
    for (int i = tid; i < 48 * 128; i += 256) {
        int row = i >> 7;             // 0..47
        int c16 = (i & 127) << 3;     // half offset, step 8
        int gate = row >> 4;
        size_t grow = (size_t)(gate * HID + cblk * 16 + (row & 15));
        cp16(smem_u32(&Bs[row * 1032 + c16]), Whh + grow * HID + c16);
    }
    cp_commit();                      // group 0 of this step's accounting

    const int ldr = tid >> 2;         // 0..63 (batch row)
    const int seg = (tid & 3) * 8;

    for (int t = 0; t < NT; ++t) {
        const __half* h16in = (t & 1) ? g_h16b : g_h16a;
        __half* h16out      = (t & 1) ? g_h16a : g_h16b;
        const __half* gA = h16in + (size_t)ldr * HID + seg;
        const uint32_t dA0 = smem_u32(&As[ldr * 40 + seg]);

        // prologue: chunks 0,1 (one commit group each)
        cp16(dA0, gA); cp_commit();
        cp16(dA0 + 2560 * 2, gA + 32); cp_commit();

        float acc[3][4] = {};
        for (int kc = 0; kc < 32; ++kc) {
            asm volatile("cp.async.wait_group 1;\n" ::: "memory"); // chunk kc ready
            __syncthreads();                                       // all done with kc-1
            if (kc + 2 < 32) {
                int nb = (kc + 2) % 3;
                cp16(dA0 + nb * 2560 * 2, gA + (kc + 2) * 32);
            }
            cp_commit();  // always one group (possibly empty) -> constant accounting
            const __half* Ac = As + (kc % 3) * 2560;
            const __half* Bc = Bs + kc * 32;
#pragma unroll
            for (int kk = 0; kk < 32; kk += 16) {
                uint32_t a[4], bb[3][2];
                int r0 = wm * 16 + g;
                a[0] = *(const uint32_t*)&Ac[r0 * 40 + kk + tg * 2];
                a[1] = *(const uint32_t*)&Ac[(r0 + 8) * 40 + kk + tg * 2];
                a[2] = *(const uint32_t*)&Ac[r0 * 40 + kk + tg * 2 + 8];
                a[3] = *(const uint32_t*)&Ac[(r0 + 8) * 40 + kk + tg * 2 + 8];
#pragma unroll
                for (int nt = 0; nt < 3; ++nt) {
                    int c0 = wn * 24 + nt * 8 + g;
                    bb[nt][0] = *(const uint32_t*)&Bc[c0 * 1032 + kk + tg * 2];
                    bb[nt][1] = *(const uint32_t*)&Bc[c0 * 1032 + kk + tg * 2 + 8];
                }
#pragma unroll
                for (int nt = 0; nt < 3; ++nt) mma16816(acc[nt], a, bb[nt]);
            }
        }

        // stage hp (64 x 48) so each thread sees its gate triple
#pragma unroll
        for (int nt = 0; nt < 3; ++nt) {
            int row = wm * 16 + g, col = wn * 24 + nt * 8 + tg * 2;
            *(float2*)&hp_s[row * 50 + col]       = make_float2(acc[nt][0], acc[nt][1]);
            *(float2*)&hp_s[(row + 8) * 50 + col] = make_float2(acc[nt][2], acc[nt][3]);
        }
        __syncthreads();

#pragma unroll
        for (int i = 0; i < 4; ++i) {
            int idx = tid + i * 256;        // 0..1023
            int b = idx >> 4, jl = idx & 15;
            int j = cblk * 16 + jl;
            size_t xbase = ((size_t)(b * NT + t)) * K3H;
            float hr = hp_s[b * 50 + jl]      + bhh[j];
            float hz = hp_s[b * 50 + 16 + jl] + bhh[HID + j];
            float hn = hp_s[b * 50 + 32 + jl] + bhh[2 * HID + j];
            float r = 1.f / (1.f + __expf(-(g_xp[xbase + j] + hr)));
            float z = 1.f / (1.f + __expf(-(g_xp[xbase + HID + j] + hz)));
            float nn = tanhf(g_xp[xbase + 2 * HID + j] + r * hn);
            float ho = g_h[b * HID + j];
            float hnew = (1.f - z) * nn + z * ho;
            g_h[b * HID + j] = hnew;
            h16out[b * HID + j] = __float2half(hnew);
            y16[((size_t)(b * NT + t)) * HID + j] = __float2half(hnew);
            if (t == NT - 1) finals[b * HID + j] = hnew;
        }

        bar_t++;
        grid_sync(bar_t);   // h published to all blocks before next timestep
    }
}

// ---------------- in-place log_softmax over V per row ----------------
__global__ __launch_bounds__(1024) void k_logsoftmax(float* __restrict__ p) {
    float* base = p + (size_t)blockIdx.x * VOC;
    const int tid = threadIdx.x;
    const int warp = tid >> 5, lane = tid & 31;
    __shared__ float red[32];

    float v[32];
    float m = -1e30f;
#pragma unroll
    for (int i = 0; i < 32; ++i) {
        int idx = tid + i * 1024;
        v[i] = (idx < VOC) ? base[idx] : -1e30f;
        m = fmaxf(m, v[i]);
    }
#pragma unroll
    for (int off = 16; off; off >>= 1) m = fmaxf(m, __shfl_xor_sync(0xffffffffu, m, off));
    if (lane == 0) red[warp] = m;
    __syncthreads();
    if (warp == 0) {
        float x = red[lane];
#pragma unroll
        for (int off = 16; off; off >>= 1) x = fmaxf(x, __shfl_xor_sync(0xffffffffu, x, off));
        red[lane] = x;
    }
    __syncthreads();
    m = red[0];
    __syncthreads();

    float s = 0.f;
#pragma unroll
    for (int i = 0; i < 32; ++i) s += __expf(v[i] - m);
#pragma unroll
    for (int off = 16; off; off >>= 1) s += __shfl_xor_sync(0xffffffffu, s, off);
    if (lane == 0) red[warp] = s;
    __syncthreads();
    if (warp == 0) {
        float x = red[lane];
#pragma unroll
        for (int off = 16; off; off >>= 1) x += __shfl_xor_sync(0xffffffffu, x, off);
        red[lane] = x;
    }
    __syncthreads();
    s = red[0];

    float lse = m + logf(s);
#pragma unroll
    for (int i = 0; i < 32; ++i) {
        int idx = tid + i * 1024;
        if (idx < VOC) base[idx] = v[i] - lse;
    }
}

// ---------------- launch ----------------
extern "C" void kernel_launch(void* const* d_in, const int* in_sizes, int n_in,
                              void* d_out, int out_size) {
    const float* enc_hidden = (const float*)d_in[1];
    const int*   target     = (const int*)d_in[2];
    const float* emb        = (const float*)d_in[3];
    const float* W_ih       = (const float*)d_in[4];
    const float* W_hh       = (const float*)d_in[5];
    const float* b_ih       = (const float*)d_in[6];
    const float* b_hh       = (const float*)d_in[7];
    const float* W_out      = (const float*)d_in[8];
    const float* b_out      = (const float*)d_in[9];
    float* out = (float*)d_out;

    cudaFuncSetAttribute(k_gru_scan, cudaFuncAttributeMaxDynamicSharedMemorySize, SCAN_SMEM);

    // 1) convert weights to fp16
    {
        int n1 = NL * K3H * HID;
        k_cvt<<<(n1 / 4 + 255) / 256, 256>>>(W_ih, 0, n1);
        k_cvt<<<(n1 / 4 + 255) / 256, 256>>>(W_hh, 1, n1);
        int n2 = VOC * HID;
        k_cvt<<<(n2 / 4 + 255) / 256, 256>>>(W_out, 2, n2);
    }

    // 2) embedding + relu
    k_embed<<<NB * NT, 256>>>(emb, target);

    // 3) layers: xp GEMM + persistent fused scan
    for (int l = 0; l < NL; ++l) {
        k_hinit<<<(NB * HID / 4) / 256, 256>>>(enc_hidden + (size_t)l * NB * HID);
        int aSel = (l == 1) ? 1 : 0;
        k_gemm<<<dim3(K3H / 64, (NB * NT) / 64), 256>>>(aSel, l, b_ih + (size_t)l * K3H,
                                                        0, nullptr, K3H);
        float* finals = out + (size_t)NB * NT * VOC + (size_t)l * NB * HID;
        k_gru_scan<<<64, 256, SCAN_SMEM>>>(l, b_hh + (size_t)l * K3H, finals);
    }

    // 4) output GEMM (logits into d_out) + log_softmax in place
    k_gemm<<<dim3(VOC / 64, (NB * NT) / 64), 256>>>(1, 3, b_out, 1, out, VOC);
    k_logsoftmax<<<NB * NT, 1024>>>(out);
}

// round 3
// speedup vs baseline: 1.2403x; 1.1345x over previous
#include <cuda_runtime.h>
#include <cuda_fp16.h>
#include <cstdint>

#define HID 1024
#define VOC 32000
#define NL  3
#define NB  64
#define NT  32
#define K3H (3*HID)

// ---------------- device scratch (static, allocation-free) ----------------
__device__ __align__(16) __half g_Wih16[NL * K3H * HID];
__device__ __align__(16) __half g_Whh16[NL * K3H * HID];
__device__ __align__(16) __half g_Wout16[VOC * HID];
__device__ __align__(16) __half g_x16a[NB * NT * HID];
__device__ __align__(16) __half g_x16b[NB * NT * HID];
__device__ __align__(16) float  g_xp[NB * NT * K3H];
__device__ __align__(16) float  g_h[NB * HID];
__device__ __align__(16) __half g_h16a[NB * HID];
__device__ __align__(16) __half g_h16b[NB * HID];

// grid barrier state (generation-based; never needs host reset)
__device__ unsigned g_bar_cnt = 0;
__device__ unsigned g_bar_gen = 0;

// ---------------- helpers ----------------
__device__ __forceinline__ uint32_t smem_u32(const void* p) {
    return (uint32_t)__cvta_generic_to_shared(p);
}
__device__ __forceinline__ void cp16(uint32_t d, const void* s) {
    asm volatile("cp.async.cg.shared.global [%0], [%1], 16;\n" :: "r"(d), "l"(s));
}
__device__ __forceinline__ void cp_commit() {
    asm volatile("cp.async.commit_group;\n" ::: "memory");
}
__device__ __forceinline__ void mma16816(float* c, const uint32_t* a, const uint32_t* b) {
    asm volatile(
        "mma.sync.aligned.m16n8k16.row.col.f32.f16.f16.f32 "
        "{%0,%1,%2,%3},{%4,%5,%6,%7},{%8,%9},{%0,%1,%2,%3};\n"
        : "+f"(c[0]), "+f"(c[1]), "+f"(c[2]), "+f"(c[3])
        : "r"(a[0]), "r"(a[1]), "r"(a[2]), "r"(a[3]), "r"(b[0]), "r"(b[1]));
}

__device__ __forceinline__ void grid_sync(unsigned target) {
    __syncthreads();
    if (threadIdx.x == 0) {
        __threadfence();
        unsigned a = atomicAdd(&g_bar_cnt, 1);
        if (a == gridDim.x - 1) {
            g_bar_cnt = 0;
            __threadfence();
            atomicExch(&g_bar_gen, target);
        } else {
            while (*(volatile unsigned*)&g_bar_gen < target) { }
        }
        __threadfence();
    }
    __syncthreads();
}

// ---------------- f32 -> f16 weight convert ----------------
__global__ void k_cvt(const float* __restrict__ src, int dstSel, int n) {
    int i = (blockIdx.x * 256 + threadIdx.x) * 4;
    if (i >= n) return;
    __half* dst = (dstSel == 0) ? g_Wih16 : (dstSel == 1) ? g_Whh16 : g_Wout16;
    float4 v = *(const float4*)(src + i);
    *(__half2*)(dst + i)     = __floats2half2_rn(v.x, v.y);
    *(__half2*)(dst + i + 2) = __floats2half2_rn(v.z, v.w);
}

// ---------------- embedding + relu -> x16a ----------------
__global__ void k_embed(const float* __restrict__ emb, const int* __restrict__ target) {
    int row = blockIdx.x;           // 0..NB*NT-1
    int b = row >> 5, t = row & 31; // NT = 32
    int id = (t == 0) ? 0 : target[b * NT + t - 1];
    const float* src = emb + (size_t)id * HID;
    __half* dst = g_x16a + (size_t)row * HID;
    int i = threadIdx.x * 4;
    float4 v = *(const float4*)(src + i);
    *(__half2*)(dst + i)     = __floats2half2_rn(fmaxf(v.x, 0.f), fmaxf(v.y, 0.f));
    *(__half2*)(dst + i + 2) = __floats2half2_rn(fmaxf(v.z, 0.f), fmaxf(v.w, 0.f));
}

// ---------------- h0 init (fp32 + fp16 copies) ----------------
__global__ void k_hinit(const float* __restrict__ src) {
    int i = (blockIdx.x * 256 + threadIdx.x) * 4;
    float4 v = *(const float4*)(src + i);
    *(float4*)(g_h + i) = v;
    *(__half2*)(g_h16a + i)     = __floats2half2_rn(v.x, v.y);
    *(__half2*)(g_h16a + i + 2) = __floats2half2_rn(v.z, v.w);
}

// ---------------- fp16 MMA GEMM: C[M,N] = A[M,K] @ B[N,K]^T + bias ----------------
// BM=128, BN=128, BK=32, 4-stage cp.async pipeline, 256 threads (8 warps, warp tile 64x32)
#define G2_STG   (128 * 40)            // halves per tile per stage
#define G2_SMEM  (4 * 2 * G2_STG * 2)  // bytes: 4 stages x (A+B) x 2B
__global__ __launch_bounds__(256, 2) void k_gemm2(int aSel, int bSel,
                                                  const float* __restrict__ bias,
                                                  int cSel, float* __restrict__ Cext, int ldc) {
    extern __shared__ __align__(16) char g2_raw[];
    __half* smA = (__half*)g2_raw;               // [4][128*40]
    __half* smB = smA + 4 * G2_STG;              // [4][128*40]

    const __half* A  = (aSel == 0) ? g_x16a : g_x16b;
    const __half* Bw = (bSel < 3) ? (g_Wih16 + (size_t)bSel * K3H * HID) : g_Wout16;
    float* C = (cSel == 0) ? g_xp : Cext;

    const int tid = threadIdx.x;
    const int bn = blockIdx.x, bm = blockIdx.y;
    const int lane = tid & 31, warp = tid >> 5;
    const int g = lane >> 2, tg = lane & 3;
    const int wy = warp >> 2, wx = warp & 3;   // wy 0..1 (64 rows), wx 0..3 (32 cols)

    const int ldr = tid >> 2;          // 0..63
    const int seg = (tid & 3) * 8;     // half offset within 32-half chunk
    const __half* gA0 = A  + (size_t)(bm * 128 + ldr) * HID + seg;
    const __half* gA1 = A  + (size_t)(bm * 128 + 64 + ldr) * HID + seg;
    const __half* gB0 = Bw + (size_t)(bn * 128 + ldr) * HID + seg;
    const __half* gB1 = Bw + (size_t)(bn * 128 + 64 + ldr) * HID + seg;
    const uint32_t dA0 = smem_u32(&smA[ldr * 40 + seg]);
    const uint32_t dA1 = smem_u32(&smA[(64 + ldr) * 40 + seg]);
    const uint32_t dB0 = smem_u32(&smB[ldr * 40 + seg]);
    const uint32_t dB1 = smem_u32(&smB[(64 + ldr) * 40 + seg]);
    const int stgB = G2_STG * 2;       // stage stride in bytes

    const int NK = HID / 32;           // 32

    // prologue: stages 0..2
#pragma unroll
    for (int s = 0; s < 3; ++s) {
        cp16(dA0 + s * stgB, gA0 + s * 32);
        cp16(dA1 + s * stgB, gA1 + s * 32);
        cp16(dB0 + s * stgB, gB0 + s * 32);
        cp16(dB1 + s * stgB, gB1 + s * 32);
        cp_commit();
    }

    float acc[4][4][4] = {};
    for (int kc = 0; kc < NK; ++kc) {
        asm volatile("cp.async.wait_group 2;\n" ::: "memory");
        __syncthreads();
        if (kc + 3 < NK) {
            int s = (kc + 3) & 3;
            cp16(dA0 + s * stgB, gA0 + (kc + 3) * 32);
            cp16(dA1 + s * stgB, gA1 + (kc + 3) * 32);
            cp16(dB0 + s * stgB, gB0 + (kc + 3) * 32);
            cp16(dB1 + s * stgB, gB1 + (kc + 3) * 32);
        }
        cp_commit();   // constant one group per iteration (possibly empty)

        const __half* As = smA + (kc & 3) * G2_STG;
        const __half* Bs = smB + (kc & 3) * G2_STG;
#pragma unroll
        for (int kk = 0; kk < 32; kk += 16) {
            uint32_t a[4][4], bb[4][2];
#pragma unroll
            for (int mt = 0; mt < 4; ++mt) {
                int r0 = wy * 64 + mt * 16 + g;
                a[mt][0] = *(const uint32_t*)&As[r0 * 40 + kk + tg * 2];
                a[mt][1] = *(const uint32_t*)&As[(r0 + 8) * 40 + kk + tg * 2];
                a[mt][2] = *(const uint32_t*)&As[r0 * 40 + kk + tg * 2 + 8];
                a[mt][3] = *(const uint32_t*)&As[(r0 + 8) * 40 + kk + tg * 2 + 8];
            }
#pragma unroll
            for (int nt = 0; nt < 4; ++nt) {
                int c0 = wx * 32 + nt * 8 + g;
                bb[nt][0] = *(const uint32_t*)&Bs[c0 * 40 + kk + tg * 2];
                bb[nt][1] = *(const uint32_t*)&Bs[c0 * 40 + kk + tg * 2 + 8];
            }
#pragma unroll
            for (int mt = 0; mt < 4; ++mt)
#pragma unroll
                for (int nt = 0; nt < 4; ++nt)
                    mma16816(acc[mt][nt], a[mt], bb[nt]);
        }
    }

#pragma unroll
    for (int mt = 0; mt < 4; ++mt) {
#pragma unroll
        for (int nt = 0; nt < 4; ++nt) {
            int row = bm * 128 + wy * 64 + mt * 16 + g;
            int col = bn * 128 + wx * 32 + nt * 8 + tg * 2;
            float b0 = bias[col], b1 = bias[col + 1];
            *(float2*)&C[(size_t)row * ldc + col] =
                make_float2(acc[mt][nt][0] + b0, acc[mt][nt][1] + b1);
            *(float2*)&C[(size_t)(row + 8) * ldc + col] =
                make_float2(acc[mt][nt][2] + b0, acc[mt][nt][3] + b1);
        }
    }
}

// ---------------- persistent GRU scan: all 32 timesteps of one layer ----------------
#define SCAN_SMEM (48*1032*2 + 3*2560*2 + 64*50*4)
__global__ __launch_bounds__(256) void k_gru_scan(int l, const float* __restrict__ bhh,
                                                  float* __restrict__ finals) {
    extern __shared__ __align__(16) char smem_raw[];
    __half* Bs = (__half*)smem_raw;          // 48 x 1032 (K-contig, 8-half pad)
    __half* As = Bs + 48 * 1032;             // 3 bufs of 64 x 40
    float* hp_s = (float*)(As + 3 * 2560);   // 64 x 50

    const __half* Whh = g_Whh16 + (size_t)l * K3H * HID;
    __half* y16 = (l == 1) ? g_x16a : g_x16b;

    const int tid = threadIdx.x;
    const int cblk = blockIdx.x; // 0..63
    const int lane = tid & 31, warp = tid >> 5;
    const int g = lane >> 2, tg = lane & 3;
    const int wm = warp >> 1, wn = warp & 1;

    unsigned bar_t = *(volatile unsigned*)&g_bar_gen;

    // load W_hh slice once: 48 rows x 1024 halves
    for (int i = tid; i < 48 * 128; i += 256) {
        int row = i >> 7;             // 0..47
        int c16 = (i & 127) << 3;     // half offset, step 8
        int gate = row >> 4;
        size_t grow = (size_t)(gate * HID + cblk * 16 + (row & 15));
        cp16(smem_u32(&Bs[row * 1032 + c16]), Whh + grow * HID + c16);
    }
    cp_commit();

    const int ldr = tid >> 2;         // 0..63 (batch row)
    const int seg = (tid & 3) * 8;

    for (int t = 0; t < NT; ++t) {
        const __half* h16in = (t & 1) ? g_h16b : g_h16a;
        __half* h16out      = (t & 1) ? g_h16a : g_h16b;
        const __half* gA = h16in + (size_t)ldr * HID + seg;
        const uint32_t dA0 = smem_u32(&As[ldr * 40 + seg]);

        cp16(dA0, gA); cp_commit();
        cp16(dA0 + 2560 * 2, gA + 32); cp_commit();

        float acc[3][4] = {};
        for (int kc = 0; kc < 32; ++kc) {
            asm volatile("cp.async.wait_group 1;\n" ::: "memory");
            __syncthreads();
            if (kc + 2 < 32) {
                int nb = (kc + 2) % 3;
                cp16(dA0 + nb * 2560 * 2, gA + (kc + 2) * 32);
            }
            cp_commit();
            const __half* Ac = As + (kc % 3) * 2560;
            const __half* Bc = Bs + kc * 32;
#pragma unroll
            for (int kk = 0; kk < 32; kk += 16) {
                uint32_t a[4], bb[3][2];
                int r0 = wm * 16 + g;
                a[0] = *(const uint32_t*)&Ac[r0 * 40 + kk + tg * 2];
                a[1] = *(const uint32_t*)&Ac[(r0 + 8) * 40 + kk + tg * 2];
                a[2] = *(const uint32_t*)&Ac[r0 * 40 + kk + tg * 2 + 8];
                a[3] = *(const uint32_t*)&Ac[(r0 + 8) * 40 + kk + tg * 2 + 8];
#pragma unroll
                for (int nt = 0; nt < 3; ++nt) {
                    int c0 = wn * 24 + nt * 8 + g;
                    bb[nt][0] = *(const uint32_t*)&Bc[c0 * 1032 + kk + tg * 2];
                    bb[nt][1] = *(const uint32_t*)&Bc[c0 * 1032 + kk + tg * 2 + 8];
                }
#pragma unroll
                for (int nt = 0; nt < 3; ++nt) mma16816(acc[nt], a, bb[nt]);
            }
        }

#pragma unroll
        for (int nt = 0; nt < 3; ++nt) {
            int row = wm * 16 + g, col = wn * 24 + nt * 8 + tg * 2;
            *(float2*)&hp_s[row * 50 + col]       = make_float2(acc[nt][0], acc[nt][1]);
            *(float2*)&hp_s[(row + 8) * 50 + col] = make_float2(acc[nt][2], acc[nt][3]);
        }
        __syncthreads();

#pragma unroll
        for (int i = 0; i < 4; ++i) {
            int idx = tid + i * 256;        // 0..1023
            int b = idx >> 4, jl = idx & 15;
            int j = cblk * 16 + jl;
            size_t xbase = ((size_t)(b * NT + t)) * K3H;
            float hr = hp_s[b * 50 + jl]      + bhh[j];
            float hz = hp_s[b * 50 + 16 + jl] + bhh[HID + j];
            float hn = hp_s[b * 50 + 32 + jl] + bhh[2 * HID + j];
            float r = 1.f / (1.f + __expf(-(g_xp[xbase + j] + hr)));
            float z = 1.f / (1.f + __expf(-(g_xp[xbase + HID + j] + hz)));
            float nn = tanhf(g_xp[xbase + 2 * HID + j] + r * hn);
            float ho = g_h[b * HID + j];
            float hnew = (1.f - z) * nn + z * ho;
            g_h[b * HID + j] = hnew;
            h16out[b * HID + j] = __float2half(hnew);
            y16[((size_t)(b * NT + t)) * HID + j] = __float2half(hnew);
            if (t == NT - 1) finals[b * HID + j] = hnew;
        }

        bar_t++;
        grid_sync(bar_t);   // h published to all blocks before next timestep
    }
}

// ---------------- in-place log_softmax over V per row ----------------
__global__ __launch_bounds__(1024) void k_logsoftmax(float* __restrict__ p) {
    float* base = p + (size_t)blockIdx.x * VOC;
    const int tid = threadIdx.x;
    const int warp = tid >> 5, lane = tid & 31;
    __shared__ float red[32];

    float v[32];
    float m = -1e30f;
#pragma unroll
    for (int i = 0; i < 32; ++i) {
        int idx = tid + i * 1024;
        v[i] = (idx < VOC) ? base[idx] : -1e30f;
        m = fmaxf(m, v[i]);
    }
#pragma unroll
    for (int off = 16; off; off >>= 1) m = fmaxf(m, __shfl_xor_sync(0xffffffffu, m, off));
    if (lane == 0) red[warp] = m;
    __syncthreads();
    if (warp == 0) {
        float x = red[lane];
#pragma unroll
        for (int off = 16; off; off >>= 1) x = fmaxf(x, __shfl_xor_sync(0xffffffffu, x, off));
        red[lane] = x;
    }
    __syncthreads();
    m = red[0];
    __syncthreads();

    float s = 0.f;
#pragma unroll
    for (int i = 0; i < 32; ++i) s += __expf(v[i] - m);
#pragma unroll
    for (int off = 16; off; off >>= 1) s += __shfl_xor_sync(0xffffffffu, s, off);
    if (lane == 0) red[warp] = s;
    __syncthreads();
    if (warp == 0) {
        float x = red[lane];
#pragma unroll
        for (int off = 16; off; off >>= 1) x += __shfl_xor_sync(0xffffffffu, x, off);
        red[lane] = x;
    }
    __syncthreads();
    s = red[0];

    float lse = m + logf(s);
#pragma unroll
    for (int i = 0; i < 32; ++i) {
        int idx = tid + i * 1024;
        if (idx < VOC) base[idx] = v[i] - lse;
    }
}

// ---------------- launch ----------------
extern "C" void kernel_launch(void* const* d_in, const int* in_sizes, int n_in,
                              void* d_out, int out_size) {
    const float* enc_hidden = (const float*)d_in[1];
    const int*   target     = (const int*)d_in[2];
    const float* emb        = (const float*)d_in[3];
    const float* W_ih       = (const float*)d_in[4];
    const float* W_hh       = (const float*)d_in[5];
    const float* b_ih       = (const float*)d_in[6];
    const float* b_hh       = (const float*)d_in[7];
    const float* W_out      = (const float*)d_in[8];
    const float* b_out      = (const float*)d_in[9];
    float* out = (float*)d_out;

    cudaFuncSetAttribute(k_gru_scan, cudaFuncAttributeMaxDynamicSharedMemorySize, SCAN_SMEM);
    cudaFuncSetAttribute(k_gemm2, cudaFuncAttributeMaxDynamicSharedMemorySize, G2_SMEM);

    // 1) convert weights to fp16
    {
        int n1 = NL * K3H * HID;
        k_cvt<<<(n1 / 4 + 255) / 256, 256>>>(W_ih, 0, n1);
        k_cvt<<<(n1 / 4 + 255) / 256, 256>>>(W_hh, 1, n1);
        int n2 = VOC * HID;
        k_cvt<<<(n2 / 4 + 255) / 256, 256>>>(W_out, 2, n2);
    }

    // 2) embedding + relu
    k_embed<<<NB * NT, 256>>>(emb, target);

    // 3) layers: xp GEMM + persistent fused scan
    for (int l = 0; l < NL; ++l) {
        k_hinit<<<(NB * HID / 4) / 256, 256>>>(enc_hidden + (size_t)l * NB * HID);
        int aSel = (l == 1) ? 1 : 0;
        k_gemm2<<<dim3(K3H / 128, (NB * NT) / 128), 256, G2_SMEM>>>(
            aSel, l, b_ih + (size_t)l * K3H, 0, nullptr, K3H);
        float* finals = out + (size_t)NB * NT * VOC + (size_t)l * NB * HID;
        k_gru_scan<<<64, 256, SCAN_SMEM>>>(l, b_hh + (size_t)l * K3H, finals);
    }

    // 4) output GEMM (logits into d_out) + log_softmax in place
    k_gemm2<<<dim3(VOC / 128, (NB * NT) / 128), 256, G2_SMEM>>>(1, 3, b_out, 1, out, VOC);
    k_logsoftmax<<<NB * NT, 1024>>>(out);
}

// round 4
// speedup vs baseline: 1.5368x; 1.2391x over previous
#include <cuda_runtime.h>
#include <cuda_fp16.h>
#include <cstdint>

#define HID 1024
#define VOC 32000
#define NL  3
#define NB  64
#define NT  32
#define K3H (3*HID)

// ---------------- device scratch (static, allocation-free) ----------------
__device__ __align__(16) __half g_Wih16[NL * K3H * HID];
__device__ __align__(16) __half g_Whh16[NL * K3H * HID];
__device__ __align__(16) __half g_Wout16[VOC * HID];
__device__ __align__(16) __half g_x16a[NB * NT * HID];
__device__ __align__(16) __half g_x16b[NB * NT * HID];
__device__ __align__(16) float  g_xp[NB * NT * K3H];
__device__ __align__(16) __half g_h16a[NB * HID];
__device__ __align__(16) __half g_h16b[NB * HID];

// grid barrier state (generation-based; never needs host reset)
__device__ unsigned g_bar_cnt = 0;
__device__ unsigned g_bar_gen = 0;

// ---------------- helpers ----------------
__device__ __forceinline__ uint32_t smem_u32(const void* p) {
    return (uint32_t)__cvta_generic_to_shared(p);
}
__device__ __forceinline__ void cp16(uint32_t d, const void* s) {
    asm volatile("cp.async.cg.shared.global [%0], [%1], 16;\n" :: "r"(d), "l"(s));
}
__device__ __forceinline__ void cp_commit() {
    asm volatile("cp.async.commit_group;\n" ::: "memory");
}
__device__ __forceinline__ void mma16816(float* c, const uint32_t* a, const uint32_t* b) {
    asm volatile(
        "mma.sync.aligned.m16n8k16.row.col.f32.f16.f16.f32 "
        "{%0,%1,%2,%3},{%4,%5,%6,%7},{%8,%9},{%0,%1,%2,%3};\n"
        : "+f"(c[0]), "+f"(c[1]), "+f"(c[2]), "+f"(c[3])
        : "r"(a[0]), "r"(a[1]), "r"(a[2]), "r"(a[3]), "r"(b[0]), "r"(b[1]));
}

__device__ __forceinline__ void grid_sync(unsigned target) {
    __syncthreads();
    if (threadIdx.x == 0) {
        __threadfence();
        unsigned a = atomicAdd(&g_bar_cnt, 1);
        if (a == gridDim.x - 1) {
            g_bar_cnt = 0;
            __threadfence();
            atomicExch(&g_bar_gen, target);
        } else {
            while (*(volatile unsigned*)&g_bar_gen < target) { }
        }
        __threadfence();
    }
    __syncthreads();
}

// ---------------- f32 -> f16 weight convert ----------------
__global__ void k_cvt(const float* __restrict__ src, int dstSel, int n) {
    int i = (blockIdx.x * 256 + threadIdx.x) * 4;
    if (i >= n) return;
    __half* dst = (dstSel == 0) ? g_Wih16 : (dstSel == 1) ? g_Whh16 : g_Wout16;
    float4 v = *(const float4*)(src + i);
    *(__half2*)(dst + i)     = __floats2half2_rn(v.x, v.y);
    *(__half2*)(dst + i + 2) = __floats2half2_rn(v.z, v.w);
}

// ---------------- embedding + relu -> x16a ----------------
__global__ void k_embed(const float* __restrict__ emb, const int* __restrict__ target) {
    int row = blockIdx.x;           // 0..NB*NT-1
    int b = row >> 5, t = row & 31; // NT = 32
    int id = (t == 0) ? 0 : target[b * NT + t - 1];
    const float* src = emb + (size_t)id * HID;
    __half* dst = g_x16a + (size_t)row * HID;
    int i = threadIdx.x * 4;
    float4 v = *(const float4*)(src + i);
    *(__half2*)(dst + i)     = __floats2half2_rn(fmaxf(v.x, 0.f), fmaxf(v.y, 0.f));
    *(__half2*)(dst + i + 2) = __floats2half2_rn(fmaxf(v.z, 0.f), fmaxf(v.w, 0.f));
}

// ---------------- h0 init (fp16 copy for GEMM A input) ----------------
__global__ void k_hinit(const float* __restrict__ src) {
    int i = (blockIdx.x * 256 + threadIdx.x) * 4;
    float4 v = *(const float4*)(src + i);
    *(__half2*)(g_h16a + i)     = __floats2half2_rn(v.x, v.y);
    *(__half2*)(g_h16a + i + 2) = __floats2half2_rn(v.z, v.w);
}

// ---------------- fp16 MMA GEMM: C[M,N] = A[M,K] @ B[N,K]^T + bias ----------------
// BM=128, BN=128, BK=32, 4-stage cp.async pipeline, 256 threads (8 warps, warp tile 64x32)
#define G2_STG   (128 * 40)            // halves per tile per stage
#define G2_SMEM  (4 * 2 * G2_STG * 2)  // bytes: 4 stages x (A+B) x 2B
__global__ __launch_bounds__(256, 2) void k_gemm2(int aSel, int bSel,
                                                  const float* __restrict__ bias,
                                                  int cSel, float* __restrict__ Cext, int ldc) {
    extern __shared__ __align__(16) char g2_raw[];
    __half* smA = (__half*)g2_raw;               // [4][128*40]
    __half* smB = smA + 4 * G2_STG;              // [4][128*40]

    const __half* A  = (aSel == 0) ? g_x16a : g_x16b;
    const __half* Bw = (bSel < 3) ? (g_Wih16 + (size_t)bSel * K3H * HID) : g_Wout16;
    float* C = (cSel == 0) ? g_xp : Cext;

    const int tid = threadIdx.x;
    const int bn = blockIdx.x, bm = blockIdx.y;
    const int lane = tid & 31, warp = tid >> 5;
    const int g = lane >> 2, tg = lane & 3;
    const int wy = warp >> 2, wx = warp & 3;   // wy 0..1 (64 rows), wx 0..3 (32 cols)

    const int ldr = tid >> 2;          // 0..63
    const int seg = (tid & 3) * 8;     // half offset within 32-half chunk
    const __half* gA0 = A  + (size_t)(bm * 128 + ldr) * HID + seg;
    const __half* gA1 = A  + (size_t)(bm * 128 + 64 + ldr) * HID + seg;
    const __half* gB0 = Bw + (size_t)(bn * 128 + ldr) * HID + seg;
    const __half* gB1 = Bw + (size_t)(bn * 128 + 64 + ldr) * HID + seg;
    const uint32_t dA0 = smem_u32(&smA[ldr * 40 + seg]);
    const uint32_t dA1 = smem_u32(&smA[(64 + ldr) * 40 + seg]);
    const uint32_t dB0 = smem_u32(&smB[ldr * 40 + seg]);
    const uint32_t dB1 = smem_u32(&smB[(64 + ldr) * 40 + seg]);
    const int stgB = G2_STG * 2;       // stage stride in bytes

    const int NK = HID / 32;           // 32

    // prologue: stages 0..2
#pragma unroll
    for (int s = 0; s < 3; ++s) {
        cp16(dA0 + s * stgB, gA0 + s * 32);
        cp16(dA1 + s * stgB, gA1 + s * 32);
        cp16(dB0 + s * stgB, gB0 + s * 32);
        cp16(dB1 + s * stgB, gB1 + s * 32);
        cp_commit();
    }

    float acc[4][4][4] = {};
    for (int kc = 0; kc < NK; ++kc) {
        asm volatile("cp.async.wait_group 2;\n" ::: "memory");
        __syncthreads();
        if (kc + 3 < NK) {
            int s = (kc + 3) & 3;
            cp16(dA0 + s * stgB, gA0 + (kc + 3) * 32);
            cp16(dA1 + s * stgB, gA1 + (kc + 3) * 32);
            cp16(dB0 + s * stgB, gB0 + (kc + 3) * 32);
            cp16(dB1 + s * stgB, gB1 + (kc + 3) * 32);
        }
        cp_commit();   // constant one group per iteration (possibly empty)

        const __half* As = smA + (kc & 3) * G2_STG;
        const __half* Bs = smB + (kc & 3) * G2_STG;
#pragma unroll
        for (int kk = 0; kk < 32; kk += 16) {
            uint32_t a[4][4], bb[4][2];
#pragma unroll
            for (int mt = 0; mt < 4; ++mt) {
                int r0 = wy * 64 + mt * 16 + g;
                a[mt][0] = *(const uint32_t*)&As[r0 * 40 + kk + tg * 2];
                a[mt][1] = *(const uint32_t*)&As[(r0 + 8) * 40 + kk + tg * 2];
                a[mt][2] = *(const uint32_t*)&As[r0 * 40 + kk + tg * 2 + 8];
                a[mt][3] = *(const uint32_t*)&As[(r0 + 8) * 40 + kk + tg * 2 + 8];
            }
#pragma unroll
            for (int nt = 0; nt < 4; ++nt) {
                int c0 = wx * 32 + nt * 8 + g;
                bb[nt][0] = *(const uint32_t*)&Bs[c0 * 40 + kk + tg * 2];
                bb[nt][1] = *(const uint32_t*)&Bs[c0 * 40 + kk + tg * 2 + 8];
            }
#pragma unroll
            for (int mt = 0; mt < 4; ++mt)
#pragma unroll
                for (int nt = 0; nt < 4; ++nt)
                    mma16816(acc[mt][nt], a[mt], bb[nt]);
        }
    }

#pragma unroll
    for (int mt = 0; mt < 4; ++mt) {
#pragma unroll
        for (int nt = 0; nt < 4; ++nt) {
            int row = bm * 128 + wy * 64 + mt * 16 + g;
            int col = bn * 128 + wx * 32 + nt * 8 + tg * 2;
            float b0 = bias[col], b1 = bias[col + 1];
            *(float2*)&C[(size_t)row * ldc + col] =
                make_float2(acc[mt][nt][0] + b0, acc[mt][nt][1] + b1);
            *(float2*)&C[(size_t)(row + 8) * ldc + col] =
                make_float2(acc[mt][nt][2] + b0, acc[mt][nt][3] + b1);
        }
    }
}

// ---------------- persistent GRU scan: all 32 timesteps of one layer ----------------
// 64 blocks x 256 threads. Block cblk owns hidden cols [cblk*16,+16) for gates r,z,n.
// W_hh slice (48x1024) resident in smem. Per step: h streamed with 8-deep cp.async
// pipeline (3 super-buffers of 4 chunks), xp slice prefetched to smem, fp32 h kept
// in smem (block-private columns), then fused gate epilogue + grid barrier.
#define SC_CH    2560                      // halves per 64x40 chunk
#define SC_BS    (48 * 1032)               // halves
#define SC_AS    (12 * SC_CH)              // halves (3 supers x 4 chunks)
#define SCAN_SMEM (SC_BS*2 + SC_AS*2 + 64*50*4 + 64*48*4 + 64*16*4)
__global__ __launch_bounds__(256) void k_gru_scan(int l, const float* __restrict__ bhh,
                                                  const float* __restrict__ enc,
                                                  float* __restrict__ finals) {
    extern __shared__ __align__(16) char smem_raw[];
    __half* Bs   = (__half*)smem_raw;            // 48 x 1032
    __half* As   = Bs + SC_BS;                   // 12 chunk bufs of 64 x 40
    float*  hp_s = (float*)(As + SC_AS);         // 64 x 50
    float*  xp_s = hp_s + 64 * 50;               // 64 x 48
    float*  h_own = xp_s + 64 * 48;              // 64 x 16 (block's fp32 h cols)

    const __half* Whh = g_Whh16 + (size_t)l * K3H * HID;
    __half* y16 = (l == 1) ? g_x16a : g_x16b;

    const int tid = threadIdx.x;
    const int cblk = blockIdx.x; // 0..63
    const int lane = tid & 31, warp = tid >> 5;
    const int g = lane >> 2, tg = lane & 3;
    const int wm = warp >> 1, wn = warp & 1;

    unsigned bar_t = *(volatile unsigned*)&g_bar_gen;

    // load W_hh slice once: 48 rows x 1024 halves
    for (int i = tid; i < 48 * 128; i += 256) {
        int row = i >> 7;             // 0..47
        int c16 = (i & 127) << 3;     // half offset, step 8
        int gate = row >> 4;
        size_t grow = (size_t)(gate * HID + cblk * 16 + (row & 15));
        cp16(smem_u32(&Bs[row * 1032 + c16]), Whh + grow * HID + c16);
    }
    cp_commit();

    // init block-private fp32 h columns from encoder_hidden
    for (int i = tid; i < 64 * 16; i += 256) {
        int b = i >> 4, jl = i & 15;
        h_own[i] = enc[(size_t)b * HID + cblk * 16 + jl];
    }

    const int ldr = tid >> 2;         // 0..63 (batch row)
    const int seg = (tid & 3) * 8;
    const uint32_t dA_base = smem_u32(&As[ldr * 40 + seg]);

    for (int t = 0; t < NT; ++t) {
        const __half* h16in = (t & 1) ? g_h16b : g_h16a;
        __half* h16out      = (t & 1) ? g_h16a : g_h16b;
        const __half* gA = h16in + (size_t)ldr * HID + seg;

        // prefetch xp slice for this step: 64 b x 3 gates x 16 floats
        for (int e = tid; e < 768; e += 256) {
            int b = e / 12, rem = e % 12;
            int gate = rem >> 2, sg = rem & 3;
            cp16(smem_u32(&xp_s[b * 48 + gate * 16 + sg * 4]),
                 g_xp + ((size_t)(b * NT + t)) * K3H + gate * HID + cblk * 16 + sg * 4);
        }
        cp_commit();

        // prologue: supers 0,1 (4 chunks each)
#pragma unroll
        for (int s = 0; s < 2; ++s) {
#pragma unroll
            for (int c = 0; c < 4; ++c)
                cp16(dA_base + (s * 4 + c) * (SC_CH * 2), gA + (s * 4 + c) * 32);
            cp_commit();
        }

        float acc[3][4] = {};
        for (int sb = 0; sb < 8; ++sb) {
            asm volatile("cp.async.wait_group 1;\n" ::: "memory");  // super sb landed
            __syncthreads();                                        // done reading sb-1's buf
            if (sb + 2 < 8) {
                int sbuf = (sb + 2) % 3;
#pragma unroll
                for (int c = 0; c < 4; ++c)
                    cp16(dA_base + (sbuf * 4 + c) * (SC_CH * 2), gA + ((sb + 2) * 4 + c) * 32);
            }
            cp_commit();   // constant group count
            const int sbase = (sb % 3) * 4;
#pragma unroll
            for (int cc = 0; cc < 4; ++cc) {
                const __half* Ac = As + (sbase + cc) * SC_CH;
                const __half* Bc = Bs + (sb * 4 + cc) * 32;
#pragma unroll
                for (int kk = 0; kk < 32; kk += 16) {
                    uint32_t a[4], bb[3][2];
                    int r0 = wm * 16 + g;
                    a[0] = *(const uint32_t*)&Ac[r0 * 40 + kk + tg * 2];
                    a[1] = *(const uint32_t*)&Ac[(r0 + 8) * 40 + kk + tg * 2];
                    a[2] = *(const uint32_t*)&Ac[r0 * 40 + kk + tg * 2 + 8];
                    a[3] = *(const uint32_t*)&Ac[(r0 + 8) * 40 + kk + tg * 2 + 8];
#pragma unroll
                    for (int nt = 0; nt < 3; ++nt) {
                        int c0 = wn * 24 + nt * 8 + g;
                        bb[nt][0] = *(const uint32_t*)&Bc[c0 * 1032 + kk + tg * 2];
                        bb[nt][1] = *(const uint32_t*)&Bc[c0 * 1032 + kk + tg * 2 + 8];
                    }
#pragma unroll
                    for (int nt = 0; nt < 3; ++nt) mma16816(acc[nt], a, bb[nt]);
                }
            }
        }

        // stage hp (64 x 48) so each thread sees its gate triple
#pragma unroll
        for (int nt = 0; nt < 3; ++nt) {
            int row = wm * 16 + g, col = wn * 24 + nt * 8 + tg * 2;
            *(float2*)&hp_s[row * 50 + col]       = make_float2(acc[nt][0], acc[nt][1]);
            *(float2*)&hp_s[(row + 8) * 50 + col] = make_float2(acc[nt][2], acc[nt][3]);
        }
        __syncthreads();

#pragma unroll
        for (int i = 0; i < 4; ++i) {
            int idx = tid + i * 256;        // 0..1023
            int b = idx >> 4, jl = idx & 15;
            int j = cblk * 16 + jl;
            float hr = hp_s[b * 50 + jl]      + bhh[j];
            float hz = hp_s[b * 50 + 16 + jl] + bhh[HID + j];
            float hn = hp_s[b * 50 + 32 + jl] + bhh[2 * HID + j];
            float r = 1.f / (1.f + __expf(-(xp_s[b * 48 + jl] + hr)));
            float z = 1.f / (1.f + __expf(-(xp_s[b * 48 + 16 + jl] + hz)));
            float nn = tanhf(xp_s[b * 48 + 32 + jl] + r * hn);
            float ho = h_own[idx];
            float hnew = (1.f - z) * nn + z * ho;
            h_own[idx] = hnew;
            h16out[(size_t)b * HID + j] = __float2half(hnew);
            y16[((size_t)(b * NT + t)) * HID + j] = __float2half(hnew);
            if (t == NT - 1) finals[(size_t)b * HID + j] = hnew;
        }

        bar_t++;
        grid_sync(bar_t);   // h published to all blocks before next timestep
    }
}

// ---------------- in-place log_softmax over V per row ----------------
__global__ __launch_bounds__(1024) void k_logsoftmax(float* __restrict__ p) {
    float* base = p + (size_t)blockIdx.x * VOC;
    const int tid = threadIdx.x;
    const int warp = tid >> 5, lane = tid & 31;
    __shared__ float red[32];

    float v[32];
    float m = -1e30f;
#pragma unroll
    for (int i = 0; i < 32; ++i) {
        int idx = tid + i * 1024;
        v[i] = (idx < VOC) ? base[idx] : -1e30f;
        m = fmaxf(m, v[i]);
    }
#pragma unroll
    for (int off = 16; off; off >>= 1) m = fmaxf(m, __shfl_xor_sync(0xffffffffu, m, off));
    if (lane == 0) red[warp] = m;
    __syncthreads();
    if (warp == 0) {
        float x = red[lane];
#pragma unroll
        for (int off = 16; off; off >>= 1) x = fmaxf(x, __shfl_xor_sync(0xffffffffu, x, off));
        red[lane] = x;
    }
    __syncthreads();
    m = red[0];
    __syncthreads();

    float s = 0.f;
#pragma unroll
    for (int i = 0; i < 32; ++i) s += __expf(v[i] - m);
#pragma unroll
    for (int off = 16; off; off >>= 1) s += __shfl_xor_sync(0xffffffffu, s, off);
    if (lane == 0) red[warp] = s;
    __syncthreads();
    if (warp == 0) {
        float x = red[lane];
#pragma unroll
        for (int off = 16; off; off >>= 1) x += __shfl_xor_sync(0xffffffffu, x, off);
        red[lane] = x;
    }
    __syncthreads();
    s = red[0];

    float lse = m + logf(s);
#pragma unroll
    for (int i = 0; i < 32; ++i) {
        int idx = tid + i * 1024;
        if (idx < VOC) base[idx] = v[i] - lse;
    }
}

// ---------------- launch ----------------
extern "C" void kernel_launch(void* const* d_in, const int* in_sizes, int n_in,
                              void* d_out, int out_size) {
    const float* enc_hidden = (const float*)d_in[1];
    const int*   target     = (const int*)d_in[2];
    const float* emb        = (const float*)d_in[3];
    const float* W_ih       = (const float*)d_in[4];
    const float* W_hh       = (const float*)d_in[5];
    const float* b_ih       = (const float*)d_in[6];
    const float* b_hh       = (const float*)d_in[7];
    const float* W_out      = (const float*)d_in[8];
    const float* b_out      = (const float*)d_in[9];
    float* out = (float*)d_out;

    cudaFuncSetAttribute(k_gru_scan, cudaFuncAttributeMaxDynamicSharedMemorySize, SCAN_SMEM);
    cudaFuncSetAttribute(k_gemm2, cudaFuncAttributeMaxDynamicSharedMemorySize, G2_SMEM);

    // 1) convert weights to fp16
    {
        int n1 = NL * K3H * HID;
        k_cvt<<<(n1 / 4 + 255) / 256, 256>>>(W_ih, 0, n1);
        k_cvt<<<(n1 / 4 + 255) / 256, 256>>>(W_hh, 1, n1);
        int n2 = VOC * HID;
        k_cvt<<<(n2 / 4 + 255) / 256, 256>>>(W_out, 2, n2);
    }

    // 2) embedding + relu
    k_embed<<<NB * NT, 256>>>(emb, target);

    // 3) layers: xp GEMM + persistent fused scan
    for (int l = 0; l < NL; ++l) {
        const float* enc_l = enc_hidden + (size_t)l * NB * HID;
        k_hinit<<<(NB * HID / 4) / 256, 256>>>(enc_l);
        int aSel = (l == 1) ? 1 : 0;
        k_gemm2<<<dim3(K3H / 128, (NB * NT) / 128), 256, G2_SMEM>>>(
            aSel, l, b_ih + (size_t)l * K3H, 0, nullptr, K3H);
        float* finals = out + (size_t)NB * NT * VOC + (size_t)l * NB * HID;
        k_gru_scan<<<64, 256, SCAN_SMEM>>>(l, b_hh + (size_t)l * K3H, enc_l, finals);
    }

    // 4) output GEMM (logits into d_out) + log_softmax in place
    k_gemm2<<<dim3(VOC / 128, (NB * NT) / 128), 256, G2_SMEM>>>(1, 3, b_out, 1, out, VOC);
    k_logsoftmax<<<NB * NT, 1024>>>(out);
}